// round 13
// baseline (speedup 1.0000x reference)
#include <cuda_runtime.h>
#include <cuda_fp16.h>
#include <math.h>
#include <stdint.h>

#define NB 256
#define NT 100
#define NI 1024
#define NH 2048
#define NO 1024

// ---------------------------------------------------------------------------
// Static device state. Spikes stored as int8 {0,1} (halves A-matrix L2 traffic).
// ---------------------------------------------------------------------------
__device__ float g_p1[NB * NI];
__device__ float g_p2[NB * NH];
__device__ int8_t g_s1[NB * NI];
__device__ int8_t g_s2[NB * NH];
__device__ float g_acc[NB * NO];
__device__ float g_df1[NI];
__device__ float g_df2[NH];
__device__ float g_tw[NT];
// 2 fp16 integer digits per weight: q = round(w*2^26) = d1*4096 + d0,
// digits in [-2048, 2048] (exact in fp16). Spike products are exact integers;
// fp32 HMMA accumulation is exact (sums <= 2^22).
__device__ __half g_W1L[2][NH * NI];
__device__ __half g_W2L[2][NO * NH];

// ---------------------------------------------------------------------------
// PTX helpers (arch-agnostic sm_80+/sm_90: cp.async / ldmatrix / mma / PDL)
// ---------------------------------------------------------------------------
__device__ __forceinline__ uint32_t smem_u32(const void* p) {
    uint32_t a;
    asm("{ .reg .u64 t; cvta.to.shared.u64 t, %1; cvt.u32.u64 %0, t; }" : "=r"(a) : "l"(p));
    return a;
}
__device__ __forceinline__ void cp16(uint32_t s, const void* g) {
    asm volatile("cp.async.cg.shared.global [%0], [%1], 16;" :: "r"(s), "l"(g));
}
#define CP_COMMIT() asm volatile("cp.async.commit_group;" ::: "memory")
#define CP_WAIT(n)  asm volatile("cp.async.wait_group %0;" :: "n"(n) : "memory")
#define GRID_WAIT()   asm volatile("griddepcontrol.wait;" ::: "memory")
#define GRID_LAUNCH() asm volatile("griddepcontrol.launch_dependents;" ::: "memory")

__device__ __forceinline__ void ldsm4(uint32_t* r, uint32_t addr) {
    asm volatile("ldmatrix.sync.aligned.m8n8.x4.shared.b16 {%0,%1,%2,%3}, [%4];"
                 : "=r"(r[0]), "=r"(r[1]), "=r"(r[2]), "=r"(r[3]) : "r"(addr));
}
__device__ __forceinline__ void ldsm2(uint32_t* r, uint32_t addr) {
    asm volatile("ldmatrix.sync.aligned.m8n8.x2.shared.b16 {%0,%1}, [%2];"
                 : "=r"(r[0]), "=r"(r[1]) : "r"(addr));
}
__device__ __forceinline__ void hmma16816(float* c, const uint32_t* a, const uint32_t* b) {
    asm volatile("mma.sync.aligned.m16n8k16.row.col.f32.f16.f16.f32 "
                 "{%0,%1,%2,%3}, {%4,%5,%6,%7}, {%8,%9}, {%0,%1,%2,%3};"
                 : "+f"(c[0]), "+f"(c[1]), "+f"(c[2]), "+f"(c[3])
                 : "r"(a[0]), "r"(a[1]), "r"(a[2]), "r"(a[3]), "r"(b[0]), "r"(b[1]));
}
#define STS128V(addr, a0, a1, a2, a3) \
    asm volatile("st.shared.v4.b32 [%0], {%1, %2, %3, %4};" \
                 :: "r"(addr), "r"(a0), "r"(a1), "r"(a2), "r"(a3) : "memory")

// Expand 4 packed spike bytes (each exactly 0 or 1) -> two fp16x2 words
// (0x3C00 = 1.0h). Exact by construction.
#define EXPAND(vv, lo, hi) do {                                   \
    uint32_t _v = (vv);                                           \
    (lo) = ((_v & 1u) | ((_v & 0x100u) << 8)) * 0x3C00u;          \
    uint32_t _w = _v >> 16;                                       \
    (hi) = ((_w & 1u) | ((_w & 0x100u) << 8)) * 0x3C00u;          \
} while (0)

// ---------------------------------------------------------------------------
// Setup kernels
// ---------------------------------------------------------------------------
__global__ void init_kernel(const float* __restrict__ cd1, const float* __restrict__ v1,
                            const float* __restrict__ cd2, const float* __restrict__ v2) {
    int idx = blockIdx.x * blockDim.x + threadIdx.x;
    if (idx < NB * NH) g_p2[idx] = 0.0f;
    if (idx < NB * NI) g_p1[idx] = 0.0f;
    if (idx < NB * NO) g_acc[idx] = 0.0f;
    if (idx < NI) {
        float vc = fminf(fmaxf(v1[0], 0.0f), 0.999f);
        float gamma = 1.0f / sqrtf(1.0f - vc * vc);
        g_df1[idx] = expf(-(gamma * fabsf(cd1[idx]) * vc));
    }
    if (idx < NH) {
        float vc = fminf(fmaxf(v2[0], 0.0f), 0.999f);
        float gamma = 1.0f / sqrtf(1.0f - vc * vc);
        g_df2[idx] = expf(-(gamma * fabsf(cd2[idx]) * vc));
    }
}

__device__ __forceinline__ void make_digits(float w, __half* out, size_t stride, size_t idx) {
    long long q = llrintf(w * 67108864.0f);  // w * 2^26
    if (q > 8388607LL) q = 8388607LL;
    if (q < -8388607LL) q = -8388607LL;
    int d0 = (int)(((q + 2048) & 4095) - 2048);
    int d1 = (int)((q - d0) >> 12);           // in [-2048, 2048], exact in fp16
    out[idx] = __int2half_rn(d0);
    out[stride + idx] = __int2half_rn(d1);
}

__global__ void limbs_kernel(const float* __restrict__ W1, const float* __restrict__ W2) {
    size_t idx = (size_t)blockIdx.x * blockDim.x + threadIdx.x;
    if (idx < (size_t)NH * NI) make_digits(W1[idx], &g_W1L[0][0], (size_t)NH * NI, idx);
    if (idx < (size_t)NO * NH) make_digits(W2[idx], &g_W2L[0][0], (size_t)NO * NH, idx);
}

__global__ void tw_kernel(const float* __restrict__ v1) {
    __shared__ float sh[128];
    int t = threadIdx.x;
    float vc = fminf(fmaxf(v1[0], 0.0f), 0.999f);
    float gamma = 1.0f / sqrtf(1.0f - vc * vc);
    float e = (t < NT) ? expf(-(gamma - 1.0f) * (float)t) : 0.0f;
    sh[t] = e;
    __syncthreads();
    for (int s = 64; s > 0; s >>= 1) {
        if (t < s) sh[t] += sh[t + s];
        __syncthreads();
    }
    if (t < NT) g_tw[t] = e / sh[0];
}

__global__ void lif1_first(const float* __restrict__ x) {
    int idx = blockIdx.x * blockDim.x + threadIdx.x;  // over NB*NI
    int b = idx / NI, i = idx % NI;
    float p = x[b * (NT * NI) + i] * g_df1[i];
    bool s = p > 1.0f;
    g_s1[idx] = s ? 1 : 0;
    g_p1[idx] = s ? 0.0f : p;
}

// ---------------------------------------------------------------------------
// HMMA GEMM + fused LIF epilogue. 256 threads, 8 warps.
// B (weight digits): 4-stage cp.async pipeline, distance 2 (R10/R12-proven).
// A (spikes): int8 in global -> coalesced LDG.128 into registers (distance 2)
// -> exact in-register expand to fp16 -> STS.128 into 2 rotating swizzled
// smem buffers (buf parity c&1; single barrier per iter is sufficient since
// buf[(c+1)&1]'s last readers finished before the iter-c barrier).
// PDL: B stages 0/1 + epilogue operands load pre-sync; A waits on GRID_WAIT;
// launch_dependents right after the MMA loop.
// WHICH==1: h = s1 @ W1^T (+b1) -> LIF2 -> s2,p2.  BM=128, BN=32, grid 128.
// WHICH==2: o = s2 @ W2^T; acc += tw*o; LIF1(t+1).  BM=64,  BN=32, grid 128.
// ---------------------------------------------------------------------------
template <int WHICH>
__global__ void __launch_bounds__(256, 1) snn_hmma(const float* __restrict__ b1,
                                                   const float* __restrict__ x, int t) {
    constexpr int K    = (WHICH == 1) ? NI : NH;
    constexpr int NOUT = (WHICH == 1) ? NH : NO;
    constexpr int BM   = (WHICH == 1) ? 128 : 64;
    constexpr int BN   = 32;
    constexpr int NT4  = (WHICH == 1) ? 2 : 1;    // n8 tiles per warp
    constexpr int G    = 2;                       // 64-col blocks per stage
    constexpr int NIT  = K / 128;                 // 8 / 16 iterations
    constexpr int ABYTES = BM * 128;              // fp16 block in smem
    constexpr int ASTG   = G * ABYTES;            // one A buffer
    constexpr int BBYTES = 2 * BN * 128;          // 8 KB per block (2 digits)
    constexpr int BSTG   = G * BBYTES;            // 16 KB per stage
    constexpr int AOFF   = 4 * BSTG;              // A buffers after 4 B stages
    constexpr int EPI    = AOFF + 2 * ASTG;       // epilogue smem offset
    constexpr int NU     = (WHICH == 1) ? 4 : 2;  // conversion units / thread
    constexpr int USH    = (WHICH == 1) ? 9 : 8;
    constexpr size_t LSTR = (size_t)NH * NI;

    const int8_t* Asp = (WHICH == 1) ? g_s1 : g_s2;
    const __half* BL  = (WHICH == 1) ? &g_W1L[0][0] : &g_W2L[0][0];

    extern __shared__ char smem[];
    uint32_t sb = smem_u32(smem);

    int tid = threadIdx.x, lane = tid & 31, w = tid >> 5;
    int m0 = blockIdx.y * BM, n0 = blockIdx.x * BN;
    int wm = (WHICH == 1) ? (w & 3) * 32 : (w & 1) * 32;
    int wn = (WHICH == 1) ? (w >> 2) * 16 : (w >> 1) * 8;

    // ---- B loader: weight-digit tiles (cp.async, swizzled rows) ----
    auto load_B = [&](int it, int stg) {
        uint32_t base = sb + stg * BSTG;
#pragma unroll
        for (int bi = 0; bi < G; bi++) {
            int kc = it * G + bi;
            uint32_t bbase = base + bi * BBYTES;
#pragma unroll
            for (int p = 0; p < 2; p++) {
                int idx = p * 256 + tid;
                int l = idx >> 8, rem = idx & 255, row = rem >> 3, q = rem & 7;
                cp16(bbase + l * (BN * 128) + row * 128 + ((q ^ (row & 7)) << 4),
                     BL + (size_t)l * LSTR + (size_t)(n0 + row) * K + kc * 64 + q * 8);
            }
        }
    };

    // ---- A register pipeline: LDG.128 int8 spikes -> expand -> STS fp16 ----
    uint4 rA[2][NU];
    auto ldgA = [&](int it, int slot) {
#pragma unroll
        for (int u = 0; u < NU; u++) {
            int unit = tid + 256 * u;
            int bi = unit >> USH;
            int rem = unit & ((1 << USH) - 1);
            int row = rem >> 2, seg = rem & 3;
            rA[slot][u] = *(const uint4*)(Asp + (size_t)(m0 + row) * K +
                                          (it * G + bi) * 64 + seg * 16);
        }
    };
    auto stsA = [&](int slot, int abuf) {
        uint32_t ab = sb + AOFF + abuf * ASTG;
#pragma unroll
        for (int u = 0; u < NU; u++) {
            int unit = tid + 256 * u;
            int bi = unit >> USH;
            int rem = unit & ((1 << USH) - 1);
            int row = rem >> 2, seg = rem & 3;
            uint4 v = rA[slot][u];
            uint32_t base = ab + bi * ABYTES + row * 128;
            int r7 = row & 7;
            uint32_t o0, o1, o2, o3;
            EXPAND(v.x, o0, o1); EXPAND(v.y, o2, o3);
            STS128V(base + (((seg * 2) ^ r7) << 4), o0, o1, o2, o3);
            EXPAND(v.z, o0, o1); EXPAND(v.w, o2, o3);
            STS128V(base + (((seg * 2 + 1) ^ r7) << 4), o0, o1, o2, o3);
        }
    };

    // ---- pre-sync phase: B stages 0/1 + epilogue operands (group 0) ----
    load_B(0, 0);
    load_B(1, 1);
    {
        uint32_t ep = sb + EPI;
        if (WHICH == 1) {
#pragma unroll
            for (int p = 0; p < 4; p++) {  // p2 tile 128x32 f32
                int idx = p * 256 + tid;
                int row = idx >> 3, q = idx & 7;
                cp16(ep + row * 128 + q * 16, g_p2 + (size_t)(m0 + row) * NH + n0 + q * 4);
            }
            if (tid < 8)       cp16(ep + 16384 + tid * 16, b1 + n0 + tid * 4);
            else if (tid < 16) cp16(ep + 16512 + (tid - 8) * 16, g_df2 + n0 + (tid - 8) * 4);
        } else {
#pragma unroll
            for (int p = 0; p < 2; p++) {  // acc + p1 (+x) tiles 64x32 f32
                int idx = p * 256 + tid;
                int row = idx >> 3, q = idx & 7;
                cp16(ep + row * 128 + q * 16, g_acc + (size_t)(m0 + row) * NO + n0 + q * 4);
                cp16(ep + 8192 + row * 128 + q * 16,
                     g_p1 + (size_t)(m0 + row) * NI + n0 + q * 4);
                if (t + 1 < NT)
                    cp16(ep + 16384 + row * 128 + q * 16,
                         x + (size_t)(m0 + row) * (NT * NI) + (size_t)(t + 1) * NI + n0 + q * 4);
            }
            if (tid < 8) cp16(ep + 24576 + tid * 16, g_df1 + n0 + tid * 4);
        }
    }
    CP_COMMIT();   // group 0

    // ---- wait for predecessor grid, then start the spike pipeline ----
    GRID_WAIT();
    ldgA(0, 0);
    ldgA(1, 1);
    stsA(0, 0);            // stalls on rA[0] scoreboard only
    CP_WAIT(0);            // B0/B1 + epilogue operands resident
    __syncthreads();       // buf0 visible to all warps

    float acc[2][2][NT4][4] = {};   // [digit][m-tile][n-tile][frag]

    for (int c = 0; c < NIT; c++) {
        if (c + 2 < NIT) { load_B(c + 2, (c + 2) & 3); CP_COMMIT(); CP_WAIT(2); }
        else if (c + 1 < NIT) { CP_WAIT(1); }
        else { CP_WAIT(0); }
        __syncthreads();   // single barrier per iteration

        if (c + 1 < NIT) stsA((c + 1) & 1, (c + 1) & 1);
        if (c + 2 < NIT) ldgA(c + 2, c & 1);

        uint32_t abase0 = sb + AOFF + (c & 1) * ASTG;
        uint32_t bbase0 = sb + (c & 3) * BSTG;
        int j = lane >> 3, r = lane & 7;

#pragma unroll
        for (int bi = 0; bi < G; bi++) {
            uint32_t abase = abase0 + bi * ABYTES;
            uint32_t bbase = bbase0 + bi * BBYTES;
#pragma unroll
            for (int ks = 0; ks < 4; ks++) {
                uint32_t a[2][4];
#pragma unroll
                for (int mt = 0; mt < 2; mt++) {
                    int row = wm + mt * 16 + ((j & 1) << 3) + r;
                    int slot = (ks * 2 + (j >> 1)) ^ (row & 7);
                    ldsm4(a[mt], abase + row * 128 + slot * 16);
                }
#pragma unroll
                for (int l = 0; l < 2; l++) {
                    if (WHICH == 1) {
                        uint32_t b[4];
                        int row = wn + ((j >> 1) << 3) + r;
                        int slot = (ks * 2 + (j & 1)) ^ (row & 7);
                        ldsm4(b, bbase + l * (BN * 128) + row * 128 + slot * 16);
#pragma unroll
                        for (int mt = 0; mt < 2; mt++) {
                            hmma16816(acc[l][mt][0], a[mt], &b[0]);
                            hmma16816(acc[l][mt][1], a[mt], &b[2]);
                        }
                    } else {
                        uint32_t b[2];
                        int row = wn + r;
                        int slot = (ks * 2 + (j & 1)) ^ (row & 7);
                        ldsm2(b, bbase + l * (BN * 128) + row * 128 + slot * 16);
#pragma unroll
                        for (int mt = 0; mt < 2; mt++)
                            hmma16816(acc[l][mt][0], a[mt], b);
                    }
                }
            }
        }
    }

    // ---- all predecessor data consumed: let the successor launch now ----
    GRID_LAUNCH();

    // ---- exact combine + fused LIF epilogue (operands from smem) ----
    const double SCALE = 1.4901161193847656e-08;  // 2^-26
    const char* ep = smem + EPI;
    int qr = lane >> 2, qc = (lane & 3) * 2;
#pragma unroll
    for (int mt = 0; mt < 2; mt++) {
#pragma unroll
        for (int h = 0; h < 2; h++) {
            int rl = wm + mt * 16 + qr + h * 8;   // local row
            int m = m0 + rl;
#pragma unroll
            for (int nt = 0; nt < NT4; nt++) {
                int cl = wn + nt * 8 + qc;        // local col
                int n = n0 + cl;
                double T0 = (double)acc[1][mt][nt][h * 2] * 4096.0 +
                            (double)acc[0][mt][nt][h * 2];
                double T1 = (double)acc[1][mt][nt][h * 2 + 1] * 4096.0 +
                            (double)acc[0][mt][nt][h * 2 + 1];
                float v0 = (float)(T0 * SCALE);
                float v1 = (float)(T1 * SCALE);
                size_t idx = (size_t)m * NOUT + n;
                if (WHICH == 1) {
                    float2 pv = *(const float2*)(ep + (rl * 32 + cl) * 4);
                    float2 bv = *(const float2*)(ep + 16384 + cl * 4);
                    float2 fv = *(const float2*)(ep + 16512 + cl * 4);
                    float p0 = pv.x * 0.9f + (v0 + bv.x) * fv.x;
                    float p1 = pv.y * 0.9f + (v1 + bv.y) * fv.y;
                    bool s0 = p0 > 0.8f, s1 = p1 > 0.8f;
                    *(float2*)(g_p2 + idx) = make_float2(s0 ? 0.f : p0, s1 ? 0.f : p1);
                    *(int16_t*)(g_s2 + idx) =
                        (int16_t)((s0 ? 1 : 0) | ((s1 ? 1 : 0) << 8));
                } else {
                    float tw = g_tw[t];
                    float2 av = *(const float2*)(ep + (rl * 32 + cl) * 4);
                    av.x += tw * v0;
                    av.y += tw * v1;
                    *(float2*)(g_acc + idx) = av;
                    if (t + 1 < NT) {
                        float2 pv = *(const float2*)(ep + 8192 + (rl * 32 + cl) * 4);
                        float2 xv = *(const float2*)(ep + 16384 + (rl * 32 + cl) * 4);
                        float2 fv = *(const float2*)(ep + 24576 + cl * 4);
                        float p0 = pv.x * 0.9f + xv.x * fv.x;
                        float p1 = pv.y * 0.9f + xv.y * fv.y;
                        bool s0 = p0 > 1.0f, s1 = p1 > 1.0f;
                        *(float2*)(g_p1 + idx) = make_float2(s0 ? 0.f : p0, s1 ? 0.f : p1);
                        *(int16_t*)(g_s1 + idx) =
                            (int16_t)((s0 ? 1 : 0) | ((s1 ? 1 : 0) << 8));
                    }
                }
            }
        }
    }
}

// Final: out = (acc + b2) * out_scale + out_bias  (sum_t tw == 1 absorbs b2).
__global__ void final_kernel(const float* __restrict__ b2, const float* __restrict__ osc,
                             const float* __restrict__ obi, float* __restrict__ out) {
    int idx = blockIdx.x * blockDim.x + threadIdx.x;
    int o = idx & (NO - 1);
    out[idx] = (g_acc[idx] + b2[o]) * osc[o] + obi[o];
}

// ---------------------------------------------------------------------------
extern "C" void kernel_launch(void* const* d_in, const int* in_sizes, int n_in,
                              void* d_out, int out_size) {
    const float* x   = (const float*)d_in[0];
    const float* cd1 = (const float*)d_in[1];
    const float* v1  = (const float*)d_in[2];
    const float* cd2 = (const float*)d_in[3];
    const float* v2  = (const float*)d_in[4];
    const float* W1  = (const float*)d_in[5];
    const float* b1  = (const float*)d_in[6];
    const float* W2  = (const float*)d_in[7];
    const float* b2  = (const float*)d_in[8];
    const float* osc = (const float*)d_in[9];
    const float* obi = (const float*)d_in[10];
    float* out = (float*)d_out;

    // GEMM1: 4*16384 (B) + 2*32768 (A bufs) + 16896 (epi) = 147968
    // GEMM2: 4*16384 (B) + 2*16384 (A bufs) + 24832 (epi) = 123136
    constexpr int SMEM1 = 4 * 16384 + 2 * 32768 + 16896;
    constexpr int SMEM2 = 4 * 16384 + 2 * 16384 + 24832;
    cudaFuncSetAttribute(snn_hmma<1>, cudaFuncAttributeMaxDynamicSharedMemorySize, SMEM1);
    cudaFuncSetAttribute(snn_hmma<2>, cudaFuncAttributeMaxDynamicSharedMemorySize, SMEM2);

    init_kernel<<<(NB * NH + 255) / 256, 256>>>(cd1, v1, cd2, v2);
    limbs_kernel<<<(NH * NI + 255) / 256, 256>>>(W1, W2);
    tw_kernel<<<1, 128>>>(v1);
    lif1_first<<<(NB * NI) / 256, 256>>>(x);

    cudaLaunchAttribute attr[1];
    attr[0].id = cudaLaunchAttributeProgrammaticStreamSerialization;
    attr[0].val.programmaticStreamSerializationAllowed = 1;

    cudaLaunchConfig_t cfg1 = {};
    cfg1.gridDim = dim3(NH / 32, NB / 128);
    cfg1.blockDim = dim3(256);
    cfg1.dynamicSmemBytes = SMEM1;
    cfg1.stream = 0;
    cfg1.attrs = attr;
    cfg1.numAttrs = 1;

    cudaLaunchConfig_t cfg2 = cfg1;
    cfg2.gridDim = dim3(NO / 32, NB / 64);
    cfg2.dynamicSmemBytes = SMEM2;

    for (int t = 0; t < NT; t++) {
        cudaLaunchKernelEx(&cfg1, snn_hmma<1>, b1, x, t);
        cudaLaunchKernelEx(&cfg2, snn_hmma<2>, b1, x, t);
    }

    final_kernel<<<(NB * NO) / 256, 256>>>(b2, osc, obi, out);
}

// round 15
// speedup vs baseline: 1.4407x; 1.4407x over previous
#include <cuda_runtime.h>
#include <cuda_fp16.h>
#include <math.h>
#include <stdint.h>

#define NB 256
#define NT 100
#define NI 1024
#define NH 2048
#define NO 1024

// ---------------------------------------------------------------------------
// Static device state.
// ---------------------------------------------------------------------------
__device__ float g_p1[NB * NI];
__device__ float g_p2[NB * NH];
__device__ __half g_s1[NB * NI];
__device__ __half g_s2[NB * NH];
__device__ float g_acc[NB * NO];
__device__ float g_df1[NI];
__device__ float g_df2[NH];
__device__ float g_tw[NT];
// 2 fp16 integer digits per weight: q = round(w*2^26) = d1*4096 + d0,
// digits in [-2048, 2048] (exact in fp16). Spike products are exact integers;
// fp32 HMMA accumulation is exact (sums <= 2^22).
__device__ __half g_W1L[2][NH * NI];
__device__ __half g_W2L[2][NO * NH];

// ---------------------------------------------------------------------------
// PTX helpers (arch-agnostic sm_80+/sm_90: cp.async / ldmatrix / mma / PDL)
// ---------------------------------------------------------------------------
__device__ __forceinline__ uint32_t smem_u32(const void* p) {
    uint32_t a;
    asm("{ .reg .u64 t; cvta.to.shared.u64 t, %1; cvt.u32.u64 %0, t; }" : "=r"(a) : "l"(p));
    return a;
}
__device__ __forceinline__ void cp16(uint32_t s, const void* g) {
    asm volatile("cp.async.cg.shared.global [%0], [%1], 16;" :: "r"(s), "l"(g));
}
#define CP_COMMIT() asm volatile("cp.async.commit_group;" ::: "memory")
#define CP_WAIT(n)  asm volatile("cp.async.wait_group %0;" :: "n"(n) : "memory")
#define GRID_WAIT()   asm volatile("griddepcontrol.wait;" ::: "memory")
#define GRID_LAUNCH() asm volatile("griddepcontrol.launch_dependents;" ::: "memory")

__device__ __forceinline__ void ldsm4(uint32_t* r, uint32_t addr) {
    asm volatile("ldmatrix.sync.aligned.m8n8.x4.shared.b16 {%0,%1,%2,%3}, [%4];"
                 : "=r"(r[0]), "=r"(r[1]), "=r"(r[2]), "=r"(r[3]) : "r"(addr));
}
__device__ __forceinline__ void ldsm2(uint32_t* r, uint32_t addr) {
    asm volatile("ldmatrix.sync.aligned.m8n8.x2.shared.b16 {%0,%1}, [%2];"
                 : "=r"(r[0]), "=r"(r[1]) : "r"(addr));
}
__device__ __forceinline__ void hmma16816(float* c, const uint32_t* a, const uint32_t* b) {
    asm volatile("mma.sync.aligned.m16n8k16.row.col.f32.f16.f16.f32 "
                 "{%0,%1,%2,%3}, {%4,%5,%6,%7}, {%8,%9}, {%0,%1,%2,%3};"
                 : "+f"(c[0]), "+f"(c[1]), "+f"(c[2]), "+f"(c[3])
                 : "r"(a[0]), "r"(a[1]), "r"(a[2]), "r"(a[3]), "r"(b[0]), "r"(b[1]));
}

// ---------------------------------------------------------------------------
// Merged setup: state zeroing (p1, p2, acc) + delay factors + weight digits
// + time weights. All components independent; tw reduction confined to block 0.
// ---------------------------------------------------------------------------
__device__ __forceinline__ void make_digits(float w, __half* out, size_t stride, size_t idx) {
    long long q = llrintf(w * 67108864.0f);  // w * 2^26
    if (q > 8388607LL) q = 8388607LL;
    if (q < -8388607LL) q = -8388607LL;
    int d0 = (int)(((q + 2048) & 4095) - 2048);
    int d1 = (int)((q - d0) >> 12);           // in [-2048, 2048], exact in fp16
    out[idx] = __int2half_rn(d0);
    out[stride + idx] = __int2half_rn(d1);
}

__global__ void setup_kernel(const float* __restrict__ cd1, const float* __restrict__ v1,
                             const float* __restrict__ cd2, const float* __restrict__ v2,
                             const float* __restrict__ W1, const float* __restrict__ W2) {
    size_t idx = (size_t)blockIdx.x * blockDim.x + threadIdx.x;
    if (idx < (size_t)NH * NI) make_digits(W1[idx], &g_W1L[0][0], (size_t)NH * NI, idx);
    if (idx < (size_t)NO * NH) make_digits(W2[idx], &g_W2L[0][0], (size_t)NO * NH, idx);
    if (idx < NB * NH) g_p2[idx] = 0.0f;
    if (idx < NB * NI) g_p1[idx] = 0.0f;
    if (idx < NB * NO) g_acc[idx] = 0.0f;   // MUST reset each call (graph replays)
    if (idx < NI) {
        float vc = fminf(fmaxf(v1[0], 0.0f), 0.999f);
        float gamma = 1.0f / sqrtf(1.0f - vc * vc);
        g_df1[idx] = expf(-(gamma * fabsf(cd1[idx]) * vc));
    }
    if (idx < NH) {
        float vc = fminf(fmaxf(v2[0], 0.0f), 0.999f);
        float gamma = 1.0f / sqrtf(1.0f - vc * vc);
        g_df2[idx] = expf(-(gamma * fabsf(cd2[idx]) * vc));
    }
    if (blockIdx.x == 0) {   // time weights (block-0 reduction)
        __shared__ float sh[128];
        int t = threadIdx.x;
        float vc = fminf(fmaxf(v1[0], 0.0f), 0.999f);
        float gamma = 1.0f / sqrtf(1.0f - vc * vc);
        float e = 0.0f;
        if (t < 128) {
            e = (t < NT) ? expf(-(gamma - 1.0f) * (float)t) : 0.0f;
            sh[t] = e;
        }
        __syncthreads();
        for (int s = 64; s > 0; s >>= 1) {
            if (t < s) sh[t] += sh[t + s];
            __syncthreads();
        }
        if (t < NT) g_tw[t] = e / sh[0];
    }
}

__global__ void lif1_first(const float* __restrict__ x) {
    int idx = blockIdx.x * blockDim.x + threadIdx.x;  // over NB*NI
    int b = idx / NI, i = idx % NI;
    float p = x[b * (NT * NI) + i] * g_df1[i];
    bool s = p > 1.0f;
    g_s1[idx] = __float2half(s ? 1.0f : 0.0f);
    g_p1[idx] = s ? 0.0f : p;
}

// ---------------------------------------------------------------------------
// HMMA GEMM + fused LIF epilogue. 256 threads, 8 warps. R12 structure:
// 4-stage cp.async pipeline, prefetch distance 2, ONE __syncthreads/iter.
// PDL: predecessor-independent loads (W digit stages 0/1 + epilogue operands,
// safe by PDL transitivity) issue before griddepcontrol.wait; only the spike
// matrix A waits. launch_dependents right after the MMA loop.
// WHICH==1: h = s1 @ W1^T (+b1) -> LIF2 -> s2,p2.  BM=128, BN=32, grid 128.
// WHICH==2: o = s2 @ W2^T; acc += tw*o; LIF1(t+1).  BM=64,  BN=32, grid 128.
//           At t==NT-1: writes out=(acc+b2)*osc+obi directly (final fused).
// ---------------------------------------------------------------------------
template <int WHICH>
__global__ void __launch_bounds__(256, 1) snn_hmma(const float* __restrict__ b1,
                                                   const float* __restrict__ x, int t,
                                                   const float* __restrict__ b2,
                                                   const float* __restrict__ osc,
                                                   const float* __restrict__ obi,
                                                   float* __restrict__ out) {
    constexpr int K    = (WHICH == 1) ? NI : NH;
    constexpr int NOUT = (WHICH == 1) ? NH : NO;
    constexpr int BM   = (WHICH == 1) ? 128 : 64;
    constexpr int BN   = 32;
    constexpr int NT4  = (WHICH == 1) ? 2 : 1;    // n8 tiles per warp
    constexpr int G    = 2;                       // 64-col blocks per stage
    constexpr int NIT  = K / (64 * G);            // 8 / 16 iterations
    constexpr int ABYTES = BM * 128;
    constexpr int BBYTES = 2 * BN * 128;
    constexpr int BLKB   = ABYTES + BBYTES;
    constexpr int STAGE  = G * BLKB;
    constexpr int EPI    = 4 * STAGE;             // epilogue smem offset
    constexpr size_t LSTR = (size_t)NH * NI;

    const __half* A  = (WHICH == 1) ? g_s1 : g_s2;
    const __half* BL = (WHICH == 1) ? &g_W1L[0][0] : &g_W2L[0][0];

    extern __shared__ char smem[];
    uint32_t sb = smem_u32(smem);

    int tid = threadIdx.x, lane = tid & 31, w = tid >> 5;
    int m0 = blockIdx.y * BM, n0 = blockIdx.x * BN;
    int wm = (WHICH == 1) ? (w & 3) * 32 : (w & 1) * 32;
    int wn = (WHICH == 1) ? (w >> 2) * 16 : (w >> 1) * 8;

    // ---- loaders (A = spikes, depends on predecessor; B = weight digits) ----
    auto load_A = [&](int it, int stg) {
        uint32_t sbase = sb + stg * STAGE;
#pragma unroll
        for (int bi = 0; bi < G; bi++) {
            int kc = it * G + bi;
            uint32_t abase = sbase + bi * BLKB;
#pragma unroll
            for (int p = 0; p < BM * 8 / 256; p++) {
                int idx = p * 256 + tid;
                int row = idx >> 3, q = idx & 7;
                cp16(abase + row * 128 + ((q ^ (row & 7)) << 4),
                     A + (size_t)(m0 + row) * K + kc * 64 + q * 8);
            }
        }
    };
    auto load_B = [&](int it, int stg) {
        uint32_t sbase = sb + stg * STAGE;
#pragma unroll
        for (int bi = 0; bi < G; bi++) {
            int kc = it * G + bi;
            uint32_t bbase = sbase + bi * BLKB + ABYTES;
#pragma unroll
            for (int p = 0; p < 2; p++) {
                int idx = p * 256 + tid;
                int l = idx >> 8, rem = idx & 255, row = rem >> 3, q = rem & 7;
                cp16(bbase + l * (BN * 128) + row * 128 + ((q ^ (row & 7)) << 4),
                     BL + (size_t)l * LSTR + (size_t)(n0 + row) * K + kc * 64 + q * 8);
            }
        }
    };

    // ---- pre-sync phase: W stages 0/1 + epilogue operands (group 0) ----
    load_B(0, 0);
    load_B(1, 1);
    {
        uint32_t ep = sb + EPI;
        if (WHICH == 1) {
#pragma unroll
            for (int p = 0; p < 4; p++) {  // p2 tile 128x32 f32
                int idx = p * 256 + tid;
                int row = idx >> 3, q = idx & 7;
                cp16(ep + row * 128 + q * 16, g_p2 + (size_t)(m0 + row) * NH + n0 + q * 4);
            }
            if (tid < 8)       cp16(ep + 16384 + tid * 16, b1 + n0 + tid * 4);
            else if (tid < 16) cp16(ep + 16512 + (tid - 8) * 16, g_df2 + n0 + (tid - 8) * 4);
        } else {
#pragma unroll
            for (int p = 0; p < 2; p++) {  // acc + p1 (+x) tiles 64x32 f32
                int idx = p * 256 + tid;
                int row = idx >> 3, q = idx & 7;
                cp16(ep + row * 128 + q * 16, g_acc + (size_t)(m0 + row) * NO + n0 + q * 4);
                cp16(ep + 8192 + row * 128 + q * 16,
                     g_p1 + (size_t)(m0 + row) * NI + n0 + q * 4);
                if (t + 1 < NT)
                    cp16(ep + 16384 + row * 128 + q * 16,
                         x + (size_t)(m0 + row) * (NT * NI) + (size_t)(t + 1) * NI + n0 + q * 4);
            }
            if (tid < 8) cp16(ep + 24576 + tid * 16, g_df1 + n0 + tid * 4);
        }
    }
    CP_COMMIT();   // group 0: B stages 0/1 + epilogue operands

    // ---- wait for predecessor grid, then load spikes ----
    GRID_WAIT();
    load_A(0, 0); CP_COMMIT();   // group: A0
    load_A(1, 1); CP_COMMIT();   // group: A1

    float acc[2][2][NT4][4] = {};   // [digit][m-tile][n-tile][frag]

    for (int c = 0; c < NIT; c++) {
        int stg = c & 3;
        if (c + 2 < NIT) {
            load_A(c + 2, (c + 2) & 3);
            load_B(c + 2, (c + 2) & 3);
            CP_COMMIT();
            CP_WAIT(2);
        }
        else if (c + 1 < NIT) { CP_WAIT(1); }
        else { CP_WAIT(0); }
        __syncthreads();   // single barrier per iteration (4-stage, dist 2)

        uint32_t sbase = sb + stg * STAGE;
        int j = lane >> 3, r = lane & 7;

#pragma unroll
        for (int bi = 0; bi < G; bi++) {
            uint32_t abase = sbase + bi * BLKB;
            uint32_t bbase = abase + ABYTES;
#pragma unroll
            for (int ks = 0; ks < 4; ks++) {
                uint32_t a[2][4];
#pragma unroll
                for (int mt = 0; mt < 2; mt++) {
                    int row = wm + mt * 16 + ((j & 1) << 3) + r;
                    int slot = (ks * 2 + (j >> 1)) ^ (row & 7);
                    ldsm4(a[mt], abase + row * 128 + slot * 16);
                }
#pragma unroll
                for (int l = 0; l < 2; l++) {
                    if (WHICH == 1) {
                        uint32_t b[4];
                        int row = wn + ((j >> 1) << 3) + r;
                        int slot = (ks * 2 + (j & 1)) ^ (row & 7);
                        ldsm4(b, bbase + l * (BN * 128) + row * 128 + slot * 16);
#pragma unroll
                        for (int mt = 0; mt < 2; mt++) {
                            hmma16816(acc[l][mt][0], a[mt], &b[0]);
                            hmma16816(acc[l][mt][1], a[mt], &b[2]);
                        }
                    } else {
                        uint32_t b[2];
                        int row = wn + r;
                        int slot = (ks * 2 + (j & 1)) ^ (row & 7);
                        ldsm2(b, bbase + l * (BN * 128) + row * 128 + slot * 16);
#pragma unroll
                        for (int mt = 0; mt < 2; mt++)
                            hmma16816(acc[l][mt][0], a[mt], b);
                    }
                }
            }
        }
    }

    // ---- all predecessor data consumed: let the successor launch now ----
    GRID_LAUNCH();

    // ---- exact combine + fused LIF epilogue (operands from smem) ----
    const double SCALE = 1.4901161193847656e-08;  // 2^-26
    const char* ep = smem + EPI;
    int qr = lane >> 2, qc = (lane & 3) * 2;
#pragma unroll
    for (int mt = 0; mt < 2; mt++) {
#pragma unroll
        for (int h = 0; h < 2; h++) {
            int rl = wm + mt * 16 + qr + h * 8;   // local row
            int m = m0 + rl;
#pragma unroll
            for (int nt = 0; nt < NT4; nt++) {
                int cl = wn + nt * 8 + qc;        // local col
                int n = n0 + cl;
                double T0 = (double)acc[1][mt][nt][h * 2] * 4096.0 +
                            (double)acc[0][mt][nt][h * 2];
                double T1 = (double)acc[1][mt][nt][h * 2 + 1] * 4096.0 +
                            (double)acc[0][mt][nt][h * 2 + 1];
                float v0 = (float)(T0 * SCALE);
                float v1 = (float)(T1 * SCALE);
                size_t idx = (size_t)m * NOUT + n;
                if (WHICH == 1) {
                    float2 pv = *(const float2*)(ep + (rl * 32 + cl) * 4);
                    float2 bv = *(const float2*)(ep + 16384 + cl * 4);
                    float2 fv = *(const float2*)(ep + 16512 + cl * 4);
                    float p0 = pv.x * 0.9f + (v0 + bv.x) * fv.x;
                    float p1 = pv.y * 0.9f + (v1 + bv.y) * fv.y;
                    bool s0 = p0 > 0.8f, s1 = p1 > 0.8f;
                    *(float2*)(g_p2 + idx) = make_float2(s0 ? 0.f : p0, s1 ? 0.f : p1);
                    *(uint32_t*)(g_s2 + idx) =
                        (s0 ? 0x3C00u : 0u) | ((s1 ? 0x3C00u : 0u) << 16);
                } else {
                    float tw = g_tw[t];
                    float2 av = *(const float2*)(ep + (rl * 32 + cl) * 4);
                    av.x += tw * v0;
                    av.y += tw * v1;
                    if (t + 1 < NT) {
                        *(float2*)(g_acc + idx) = av;
                        float2 pv = *(const float2*)(ep + 8192 + (rl * 32 + cl) * 4);
                        float2 xv = *(const float2*)(ep + 16384 + (rl * 32 + cl) * 4);
                        float2 fv = *(const float2*)(ep + 24576 + cl * 4);
                        float p0 = pv.x * 0.9f + xv.x * fv.x;
                        float p1 = pv.y * 0.9f + xv.y * fv.y;
                        bool s0 = p0 > 1.0f, s1 = p1 > 1.0f;
                        *(float2*)(g_p1 + idx) = make_float2(s0 ? 0.f : p0, s1 ? 0.f : p1);
                        *(uint32_t*)(g_s1 + idx) =
                            (s0 ? 0x3C00u : 0u) | ((s1 ? 0x3C00u : 0u) << 16);
                    } else {
                        // final step: out = (acc + b2) * out_scale + out_bias
                        float2 b2v = *(const float2*)(b2 + n);
                        float2 scv = *(const float2*)(osc + n);
                        float2 obv = *(const float2*)(obi + n);
                        float2 ov;
                        ov.x = (av.x + b2v.x) * scv.x + obv.x;
                        ov.y = (av.y + b2v.y) * scv.y + obv.y;
                        *(float2*)(out + idx) = ov;
                    }
                }
            }
        }
    }
}

// ---------------------------------------------------------------------------
extern "C" void kernel_launch(void* const* d_in, const int* in_sizes, int n_in,
                              void* d_out, int out_size) {
    const float* x   = (const float*)d_in[0];
    const float* cd1 = (const float*)d_in[1];
    const float* v1  = (const float*)d_in[2];
    const float* cd2 = (const float*)d_in[3];
    const float* v2  = (const float*)d_in[4];
    const float* W1  = (const float*)d_in[5];
    const float* b1  = (const float*)d_in[6];
    const float* W2  = (const float*)d_in[7];
    const float* b2  = (const float*)d_in[8];
    const float* osc = (const float*)d_in[9];
    const float* obi = (const float*)d_in[10];
    float* out = (float*)d_out;

    // GEMM1: 4 stages * 2 * (16384+8192) + epi (16896) = 213504
    // GEMM2: 4 stages * 2 * (8192+8192)  + epi (24832) = 155904
    constexpr int SMEM1 = 4 * 2 * (128 * 128 + 2 * 32 * 128) + 16896;
    constexpr int SMEM2 = 4 * 2 * (64 * 128 + 2 * 32 * 128) + 24832;
    cudaFuncSetAttribute(snn_hmma<1>, cudaFuncAttributeMaxDynamicSharedMemorySize, SMEM1);
    cudaFuncSetAttribute(snn_hmma<2>, cudaFuncAttributeMaxDynamicSharedMemorySize, SMEM2);

    setup_kernel<<<(NH * NI + 255) / 256, 256>>>(cd1, v1, cd2, v2, W1, W2);
    lif1_first<<<(NB * NI) / 256, 256>>>(x);

    // PDL launches: successor may start (pre-sync phase) once the predecessor
    // signals launch_dependents; data dependency enforced by griddepcontrol.wait.
    cudaLaunchAttribute attr[1];
    attr[0].id = cudaLaunchAttributeProgrammaticStreamSerialization;
    attr[0].val.programmaticStreamSerializationAllowed = 1;

    cudaLaunchConfig_t cfg1 = {};
    cfg1.gridDim = dim3(NH / 32, NB / 128);
    cfg1.blockDim = dim3(256);
    cfg1.dynamicSmemBytes = SMEM1;
    cfg1.stream = 0;
    cfg1.attrs = attr;
    cfg1.numAttrs = 1;

    cudaLaunchConfig_t cfg2 = cfg1;
    cfg2.gridDim = dim3(NO / 32, NB / 64);
    cfg2.dynamicSmemBytes = SMEM2;

    for (int t = 0; t < NT; t++) {
        cudaLaunchKernelEx(&cfg1, snn_hmma<1>, b1, x, t, b2, osc, obi, out);
        cudaLaunchKernelEx(&cfg2, snn_hmma<2>, b1, x, t, b2, osc, obi, out);
    }
}

// round 16
// speedup vs baseline: 1.5185x; 1.0540x over previous
#include <cuda_runtime.h>
#include <cuda_fp16.h>
#include <math.h>
#include <stdint.h>

#define NB 256
#define NT 100
#define NI 1024
#define NH 2048
#define NO 1024

// ---------------------------------------------------------------------------
// Static device state.
// ---------------------------------------------------------------------------
__device__ float g_p1[NB * NI];
__device__ float g_p2[NB * NH];
__device__ __half g_s1[NB * NI];
__device__ __half g_s2[NB * NH];
__device__ float g_acc[NB * NO];
__device__ float g_df1[NI];
__device__ float g_df2[NH];
__device__ float g_tw[NT];
// 2 fp16 integer digits per weight: q = round(w*2^26) = d1*4096 + d0,
// digits in [-2048, 2048] (exact in fp16). Spike products are exact integers;
// fp32 HMMA accumulation is exact (sums <= 2^22 per half-K, 2^23 combined).
__device__ __half g_W1L[2][NH * NI];
__device__ __half g_W2L[2][NO * NH];

// ---------------------------------------------------------------------------
// PTX helpers (arch-agnostic sm_80+/sm_90: cp.async / ldmatrix / mma / PDL)
// ---------------------------------------------------------------------------
__device__ __forceinline__ uint32_t smem_u32(const void* p) {
    uint32_t a;
    asm("{ .reg .u64 t; cvta.to.shared.u64 t, %1; cvt.u32.u64 %0, t; }" : "=r"(a) : "l"(p));
    return a;
}
__device__ __forceinline__ void cp16(uint32_t s, const void* g) {
    asm volatile("cp.async.cg.shared.global [%0], [%1], 16;" :: "r"(s), "l"(g));
}
#define CP_COMMIT() asm volatile("cp.async.commit_group;" ::: "memory")
#define CP_WAIT(n)  asm volatile("cp.async.wait_group %0;" :: "n"(n) : "memory")
#define GRID_WAIT()   asm volatile("griddepcontrol.wait;" ::: "memory")
#define GRID_LAUNCH() asm volatile("griddepcontrol.launch_dependents;" ::: "memory")

__device__ __forceinline__ void ldsm4(uint32_t* r, uint32_t addr) {
    asm volatile("ldmatrix.sync.aligned.m8n8.x4.shared.b16 {%0,%1,%2,%3}, [%4];"
                 : "=r"(r[0]), "=r"(r[1]), "=r"(r[2]), "=r"(r[3]) : "r"(addr));
}
__device__ __forceinline__ void hmma16816(float* c, const uint32_t* a, const uint32_t* b) {
    asm volatile("mma.sync.aligned.m16n8k16.row.col.f32.f16.f16.f32 "
                 "{%0,%1,%2,%3}, {%4,%5,%6,%7}, {%8,%9}, {%0,%1,%2,%3};"
                 : "+f"(c[0]), "+f"(c[1]), "+f"(c[2]), "+f"(c[3])
                 : "r"(a[0]), "r"(a[1]), "r"(a[2]), "r"(a[3]), "r"(b[0]), "r"(b[1]));
}

// ---------------------------------------------------------------------------
// Merged setup: state zeroing (p1, p2, acc) + delay factors + weight digits
// + time weights. All components independent; tw reduction confined to block 0.
// ---------------------------------------------------------------------------
__device__ __forceinline__ void make_digits(float w, __half* out, size_t stride, size_t idx) {
    long long q = llrintf(w * 67108864.0f);  // w * 2^26
    if (q > 8388607LL) q = 8388607LL;
    if (q < -8388607LL) q = -8388607LL;
    int d0 = (int)(((q + 2048) & 4095) - 2048);
    int d1 = (int)((q - d0) >> 12);           // in [-2048, 2048], exact in fp16
    out[idx] = __int2half_rn(d0);
    out[stride + idx] = __int2half_rn(d1);
}

__global__ void setup_kernel(const float* __restrict__ cd1, const float* __restrict__ v1,
                             const float* __restrict__ cd2, const float* __restrict__ v2,
                             const float* __restrict__ W1, const float* __restrict__ W2) {
    size_t idx = (size_t)blockIdx.x * blockDim.x + threadIdx.x;
    if (idx < (size_t)NH * NI) make_digits(W1[idx], &g_W1L[0][0], (size_t)NH * NI, idx);
    if (idx < (size_t)NO * NH) make_digits(W2[idx], &g_W2L[0][0], (size_t)NO * NH, idx);
    if (idx < NB * NH) g_p2[idx] = 0.0f;
    if (idx < NB * NI) g_p1[idx] = 0.0f;
    if (idx < NB * NO) g_acc[idx] = 0.0f;   // MUST reset each call (graph replays)
    if (idx < NI) {
        float vc = fminf(fmaxf(v1[0], 0.0f), 0.999f);
        float gamma = 1.0f / sqrtf(1.0f - vc * vc);
        g_df1[idx] = expf(-(gamma * fabsf(cd1[idx]) * vc));
    }
    if (idx < NH) {
        float vc = fminf(fmaxf(v2[0], 0.0f), 0.999f);
        float gamma = 1.0f / sqrtf(1.0f - vc * vc);
        g_df2[idx] = expf(-(gamma * fabsf(cd2[idx]) * vc));
    }
    if (blockIdx.x == 0) {   // time weights (block-0 reduction)
        __shared__ float sh[128];
        int t = threadIdx.x;
        float vc = fminf(fmaxf(v1[0], 0.0f), 0.999f);
        float gamma = 1.0f / sqrtf(1.0f - vc * vc);
        float e = 0.0f;
        if (t < 128) {
            e = (t < NT) ? expf(-(gamma - 1.0f) * (float)t) : 0.0f;
            sh[t] = e;
        }
        __syncthreads();
        for (int s = 64; s > 0; s >>= 1) {
            if (t < s) sh[t] += sh[t + s];
            __syncthreads();
        }
        if (t < NT) g_tw[t] = e / sh[0];
    }
}

__global__ void lif1_first(const float* __restrict__ x) {
    int idx = blockIdx.x * blockDim.x + threadIdx.x;  // over NB*NI
    int b = idx / NI, i = idx % NI;
    float p = x[b * (NT * NI) + i] * g_df1[i];
    bool s = p > 1.0f;
    g_s1[idx] = __float2half(s ? 1.0f : 0.0f);
    g_p1[idx] = s ? 0.0f : p;
}

// ---------------------------------------------------------------------------
// HMMA GEMM + fused LIF epilogue. 256 threads, 8 warps.
// 4-stage cp.async pipeline, prefetch distance 2, ONE __syncthreads/iter.
// PDL: W digit stages 0/1 + epilogue operands load pre-GRID_WAIT; only the
// spike matrix A waits. launch_dependents right after the MMA loop.
// WHICH==1: h = s1 @ W1^T (+b1) -> LIF2 -> s2,p2.  BM=128, BN=32, grid 128.
//           Warps 4(M)x2(N), warp tile 32x16, full K per warp.
// WHICH==2: o = s2 @ W2^T; acc += tw*o; LIF1(t+1).  BM=64,  BN=32, grid 128.
//           Warps 2(M)x2(N)x2(K-split): warp tile 32x16, each warp covers its
//           64-col block of every 128-col stage (half of K). Exact fp32-integer
//           accumulators are pair-summed through smem at the end — bit-identical
//           to the full-K result. kz=0 warps run the epilogue.
//           At t==NT-1: writes out=(acc+b2)*osc+obi directly (final fused).
// ---------------------------------------------------------------------------
template <int WHICH>
__global__ void __launch_bounds__(256, 1) snn_hmma(const float* __restrict__ b1,
                                                   const float* __restrict__ x, int t,
                                                   const float* __restrict__ b2,
                                                   const float* __restrict__ osc,
                                                   const float* __restrict__ obi,
                                                   float* __restrict__ out) {
    constexpr int K    = (WHICH == 1) ? NI : NH;
    constexpr int NOUT = (WHICH == 1) ? NH : NO;
    constexpr int BM   = (WHICH == 1) ? 128 : 64;
    constexpr int BN   = 32;
    constexpr int NT4  = 2;                       // n8 tiles per warp (both)
    constexpr int G    = 2;                       // 64-col blocks per stage
    constexpr int NIT  = K / (64 * G);            // 8 / 16 iterations
    constexpr int ABYTES = BM * 128;
    constexpr int BBYTES = 2 * BN * 128;
    constexpr int BLKB   = ABYTES + BBYTES;
    constexpr int STAGE  = G * BLKB;
    constexpr int EPI    = 4 * STAGE;             // epilogue smem offset
    constexpr int RED    = EPI + 24832;           // reduction area (WHICH==2)
    constexpr size_t LSTR = (size_t)NH * NI;

    const __half* A  = (WHICH == 1) ? g_s1 : g_s2;
    const __half* BL = (WHICH == 1) ? &g_W1L[0][0] : &g_W2L[0][0];

    extern __shared__ char smem[];
    uint32_t sb = smem_u32(smem);

    int tid = threadIdx.x, lane = tid & 31, w = tid >> 5;
    int m0 = blockIdx.y * BM, n0 = blockIdx.x * BN;
    // warp mapping: GEMM1 4(M)x2(N); GEMM2 kz=w>>2 (K-half), 2(M)x2(N) within.
    int kz = (WHICH == 1) ? 0 : (w >> 2);
    int wm = (WHICH == 1) ? (w & 3) * 32 : ((w >> 1) & 1) * 32;
    int wn = (WHICH == 1) ? (w >> 2) * 16 : (w & 1) * 16;

    // ---- loaders (A = spikes, depends on predecessor; B = weight digits) ----
    auto load_A = [&](int it, int stg) {
        uint32_t sbase = sb + stg * STAGE;
#pragma unroll
        for (int bi = 0; bi < G; bi++) {
            int kc = it * G + bi;
            uint32_t abase = sbase + bi * BLKB;
#pragma unroll
            for (int p = 0; p < BM * 8 / 256; p++) {
                int idx = p * 256 + tid;
                int row = idx >> 3, q = idx & 7;
                cp16(abase + row * 128 + ((q ^ (row & 7)) << 4),
                     A + (size_t)(m0 + row) * K + kc * 64 + q * 8);
            }
        }
    };
    auto load_B = [&](int it, int stg) {
        uint32_t sbase = sb + stg * STAGE;
#pragma unroll
        for (int bi = 0; bi < G; bi++) {
            int kc = it * G + bi;
            uint32_t bbase = sbase + bi * BLKB + ABYTES;
#pragma unroll
            for (int p = 0; p < 2; p++) {
                int idx = p * 256 + tid;
                int l = idx >> 8, rem = idx & 255, row = rem >> 3, q = rem & 7;
                cp16(bbase + l * (BN * 128) + row * 128 + ((q ^ (row & 7)) << 4),
                     BL + (size_t)l * LSTR + (size_t)(n0 + row) * K + kc * 64 + q * 8);
            }
        }
    };

    // ---- pre-sync phase: W stages 0/1 + epilogue operands (group 0) ----
    load_B(0, 0);
    load_B(1, 1);
    {
        uint32_t ep = sb + EPI;
        if (WHICH == 1) {
#pragma unroll
            for (int p = 0; p < 4; p++) {  // p2 tile 128x32 f32
                int idx = p * 256 + tid;
                int row = idx >> 3, q = idx & 7;
                cp16(ep + row * 128 + q * 16, g_p2 + (size_t)(m0 + row) * NH + n0 + q * 4);
            }
            if (tid < 8)       cp16(ep + 16384 + tid * 16, b1 + n0 + tid * 4);
            else if (tid < 16) cp16(ep + 16512 + (tid - 8) * 16, g_df2 + n0 + (tid - 8) * 4);
        } else {
#pragma unroll
            for (int p = 0; p < 2; p++) {  // acc + p1 (+x) tiles 64x32 f32
                int idx = p * 256 + tid;
                int row = idx >> 3, q = idx & 7;
                cp16(ep + row * 128 + q * 16, g_acc + (size_t)(m0 + row) * NO + n0 + q * 4);
                cp16(ep + 8192 + row * 128 + q * 16,
                     g_p1 + (size_t)(m0 + row) * NI + n0 + q * 4);
                if (t + 1 < NT)
                    cp16(ep + 16384 + row * 128 + q * 16,
                         x + (size_t)(m0 + row) * (NT * NI) + (size_t)(t + 1) * NI + n0 + q * 4);
            }
            if (tid < 8) cp16(ep + 24576 + tid * 16, g_df1 + n0 + tid * 4);
        }
    }
    CP_COMMIT();   // group 0: B stages 0/1 + epilogue operands

    // ---- wait for predecessor grid, then load spikes ----
    GRID_WAIT();
    load_A(0, 0); CP_COMMIT();   // group: A0
    load_A(1, 1); CP_COMMIT();   // group: A1

    float acc[2][2][NT4][4] = {};   // [digit][m-tile][n-tile][frag]

    for (int c = 0; c < NIT; c++) {
        int stg = c & 3;
        if (c + 2 < NIT) {
            load_A(c + 2, (c + 2) & 3);
            load_B(c + 2, (c + 2) & 3);
            CP_COMMIT();
            CP_WAIT(2);
        }
        else if (c + 1 < NIT) { CP_WAIT(1); }
        else { CP_WAIT(0); }
        __syncthreads();   // single barrier per iteration (4-stage, dist 2)

        uint32_t sbase = sb + stg * STAGE;
        int j = lane >> 3, r = lane & 7;

#pragma unroll
        for (int bi0 = 0; bi0 < ((WHICH == 1) ? G : 1); bi0++) {
            int bi = (WHICH == 1) ? bi0 : kz;   // split-K: one block per warp
            uint32_t abase = sbase + bi * BLKB;
            uint32_t bbase = abase + ABYTES;
#pragma unroll
            for (int ks = 0; ks < 4; ks++) {
                uint32_t a[2][4];
#pragma unroll
                for (int mt = 0; mt < 2; mt++) {
                    int row = wm + mt * 16 + ((j & 1) << 3) + r;
                    int slot = (ks * 2 + (j >> 1)) ^ (row & 7);
                    ldsm4(a[mt], abase + row * 128 + slot * 16);
                }
#pragma unroll
                for (int l = 0; l < 2; l++) {
                    uint32_t b[4];
                    int row = wn + ((j >> 1) << 3) + r;
                    int slot = (ks * 2 + (j & 1)) ^ (row & 7);
                    ldsm4(b, bbase + l * (BN * 128) + row * 128 + slot * 16);
#pragma unroll
                    for (int mt = 0; mt < 2; mt++) {
                        hmma16816(acc[l][mt][0], a[mt], &b[0]);
                        hmma16816(acc[l][mt][1], a[mt], &b[2]);
                    }
                }
            }
        }
    }

    // ---- all predecessor data consumed: let the successor launch now ----
    GRID_LAUNCH();

    // ---- WHICH==2: exact split-K pair reduction through smem ----
    if (WHICH == 2) {
        float* red = (float*)(smem + RED);
        if (w >= 4) {   // kz=1 warps publish their exact-integer accumulators
            float* dst = red + (w - 4) * 1024 + lane;
#pragma unroll
            for (int l = 0; l < 2; l++)
#pragma unroll
                for (int mt = 0; mt < 2; mt++)
#pragma unroll
                    for (int nt = 0; nt < NT4; nt++)
#pragma unroll
                        for (int k4 = 0; k4 < 4; k4++)
                            dst[(((l * 2 + mt) * 2 + nt) * 4 + k4) * 32] =
                                acc[l][mt][nt][k4];
        }
        __syncthreads();
        if (w >= 4) return;   // kz=1 warps done
        const float* src = red + w * 1024 + lane;
#pragma unroll
        for (int l = 0; l < 2; l++)
#pragma unroll
            for (int mt = 0; mt < 2; mt++)
#pragma unroll
                for (int nt = 0; nt < NT4; nt++)
#pragma unroll
                    for (int k4 = 0; k4 < 4; k4++)
                        acc[l][mt][nt][k4] +=
                            src[(((l * 2 + mt) * 2 + nt) * 4 + k4) * 32];
    }

    // ---- exact combine + fused LIF epilogue (operands from smem) ----
    const double SCALE = 1.4901161193847656e-08;  // 2^-26
    const char* ep = smem + EPI;
    int qr = lane >> 2, qc = (lane & 3) * 2;
#pragma unroll
    for (int mt = 0; mt < 2; mt++) {
#pragma unroll
        for (int h = 0; h < 2; h++) {
            int rl = wm + mt * 16 + qr + h * 8;   // local row
            int m = m0 + rl;
#pragma unroll
            for (int nt = 0; nt < NT4; nt++) {
                int cl = wn + nt * 8 + qc;        // local col
                int n = n0 + cl;
                double T0 = (double)acc[1][mt][nt][h * 2] * 4096.0 +
                            (double)acc[0][mt][nt][h * 2];
                double T1 = (double)acc[1][mt][nt][h * 2 + 1] * 4096.0 +
                            (double)acc[0][mt][nt][h * 2 + 1];
                float v0 = (float)(T0 * SCALE);
                float v1 = (float)(T1 * SCALE);
                size_t idx = (size_t)m * NOUT + n;
                if (WHICH == 1) {
                    float2 pv = *(const float2*)(ep + (rl * 32 + cl) * 4);
                    float2 bv = *(const float2*)(ep + 16384 + cl * 4);
                    float2 fv = *(const float2*)(ep + 16512 + cl * 4);
                    float p0 = pv.x * 0.9f + (v0 + bv.x) * fv.x;
                    float p1 = pv.y * 0.9f + (v1 + bv.y) * fv.y;
                    bool s0 = p0 > 0.8f, s1 = p1 > 0.8f;
                    *(float2*)(g_p2 + idx) = make_float2(s0 ? 0.f : p0, s1 ? 0.f : p1);
                    *(uint32_t*)(g_s2 + idx) =
                        (s0 ? 0x3C00u : 0u) | ((s1 ? 0x3C00u : 0u) << 16);
                } else {
                    float tw = g_tw[t];
                    float2 av = *(const float2*)(ep + (rl * 32 + cl) * 4);
                    av.x += tw * v0;
                    av.y += tw * v1;
                    if (t + 1 < NT) {
                        *(float2*)(g_acc + idx) = av;
                        float2 pv = *(const float2*)(ep + 8192 + (rl * 32 + cl) * 4);
                        float2 xv = *(const float2*)(ep + 16384 + (rl * 32 + cl) * 4);
                        float2 fv = *(const float2*)(ep + 24576 + cl * 4);
                        float p0 = pv.x * 0.9f + xv.x * fv.x;
                        float p1 = pv.y * 0.9f + xv.y * fv.y;
                        bool s0 = p0 > 1.0f, s1 = p1 > 1.0f;
                        *(float2*)(g_p1 + idx) = make_float2(s0 ? 0.f : p0, s1 ? 0.f : p1);
                        *(uint32_t*)(g_s1 + idx) =
                            (s0 ? 0x3C00u : 0u) | ((s1 ? 0x3C00u : 0u) << 16);
                    } else {
                        // final step: out = (acc + b2) * out_scale + out_bias
                        float2 b2v = *(const float2*)(b2 + n);
                        float2 scv = *(const float2*)(osc + n);
                        float2 obv = *(const float2*)(obi + n);
                        float2 ov;
                        ov.x = (av.x + b2v.x) * scv.x + obv.x;
                        ov.y = (av.y + b2v.y) * scv.y + obv.y;
                        *(float2*)(out + idx) = ov;
                    }
                }
            }
        }
    }
}

// ---------------------------------------------------------------------------
extern "C" void kernel_launch(void* const* d_in, const int* in_sizes, int n_in,
                              void* d_out, int out_size) {
    const float* x   = (const float*)d_in[0];
    const float* cd1 = (const float*)d_in[1];
    const float* v1  = (const float*)d_in[2];
    const float* cd2 = (const float*)d_in[3];
    const float* v2  = (const float*)d_in[4];
    const float* W1  = (const float*)d_in[5];
    const float* b1  = (const float*)d_in[6];
    const float* W2  = (const float*)d_in[7];
    const float* b2  = (const float*)d_in[8];
    const float* osc = (const float*)d_in[9];
    const float* obi = (const float*)d_in[10];
    float* out = (float*)d_out;

    // GEMM1: 4 stages * 2 * (16384+8192) + epi (16896)            = 213504
    // GEMM2: 4 stages * 2 * (8192+8192)  + epi (24832) + red (16K) = 172288
    constexpr int SMEM1 = 4 * 2 * (128 * 128 + 2 * 32 * 128) + 16896;
    constexpr int SMEM2 = 4 * 2 * (64 * 128 + 2 * 32 * 128) + 24832 + 16384;
    cudaFuncSetAttribute(snn_hmma<1>, cudaFuncAttributeMaxDynamicSharedMemorySize, SMEM1);
    cudaFuncSetAttribute(snn_hmma<2>, cudaFuncAttributeMaxDynamicSharedMemorySize, SMEM2);

    setup_kernel<<<(NH * NI + 255) / 256, 256>>>(cd1, v1, cd2, v2, W1, W2);
    lif1_first<<<(NB * NI) / 256, 256>>>(x);

    cudaLaunchAttribute attr[1];
    attr[0].id = cudaLaunchAttributeProgrammaticStreamSerialization;
    attr[0].val.programmaticStreamSerializationAllowed = 1;

    cudaLaunchConfig_t cfg1 = {};
    cfg1.gridDim = dim3(NH / 32, NB / 128);
    cfg1.blockDim = dim3(256);
    cfg1.dynamicSmemBytes = SMEM1;
    cfg1.stream = 0;
    cfg1.attrs = attr;
    cfg1.numAttrs = 1;

    cudaLaunchConfig_t cfg2 = cfg1;
    cfg2.gridDim = dim3(NO / 32, NB / 64);
    cfg2.dynamicSmemBytes = SMEM2;

    for (int t = 0; t < NT; t++) {
        cudaLaunchKernelEx(&cfg1, snn_hmma<1>, b1, x, t, b2, osc, obi, out);
        cudaLaunchKernelEx(&cfg2, snn_hmma<2>, b1, x, t, b2, osc, obi, out);
    }
}